// round 4
// baseline (speedup 1.0000x reference)
#include <cuda_runtime.h>
#include <math.h>

// Problem constants
#define PARTS   5
#define BATCH   128
#define SEQ     300
#define DP      30
#define HID     512
#define CLASSES 60
#define IN_DIM  150          // PARTS*DP
#define GATES3  1536         // 3*HID
#define NB      8192         // PARTS*GATES3 + HID   (gate cols + o_pre cols)
#define KA      662          // IN_DIM + HID
#define KP      672          // KA padded to multiple of 16

// GEMM tiling
#define BK 16
#define BN 64
#define TM 8
#define TN 4

// Scratch (device globals — no allocation allowed)
__device__ float g_W[KP * NB];              // packed weights, 21.7 MB
__device__ float g_bias[NB];
__device__ float g_A[BATCH * KP];           // [x_flat | h | pad] per batch row
__device__ float g_G[BATCH * NB];           // gate pre-activations
__device__ float g_c[BATCH * PARTS * HID];  // per-part cell state

__device__ __forceinline__ float sigf(float x) { return 1.0f / (1.0f + expf(-x)); }

// ---------------------------------------------------------------------------
// Pack W once per launch (idempotent, deterministic).
// Column layout: n in [0, 7680): part p = n/1536, gate index gi = n%1536
//                n in [7680, 8192): o_pre column j = n-7680
// Row layout:    k in [0,150): x_flat (part p occupies k in [p*30, p*30+30))
//                k in [150,662): h ; k in [662,672): zero pad
// ---------------------------------------------------------------------------
__global__ void pack_kernel(const float* __restrict__ Wx, const float* __restrict__ Wh,
                            const float* __restrict__ Wxo, const float* __restrict__ Who) {
    int idx = blockIdx.x * blockDim.x + threadIdx.x;
    const int total = KP * NB;
    for (; idx < total; idx += gridDim.x * blockDim.x) {
        int k = idx / NB;
        int n = idx % NB;
        float v = 0.0f;
        if (n < PARTS * GATES3) {
            int p  = n / GATES3;
            int gi = n % GATES3;
            if (k < IN_DIM) {
                if (k >= p * DP && k < p * DP + DP)
                    v = Wx[k * GATES3 + gi];          // (p*DP + d) == k
            } else if (k < KA) {
                v = Wh[(p * HID + (k - IN_DIM)) * GATES3 + gi];
            }
        } else {
            int j = n - PARTS * GATES3;
            if (k < IN_DIM)      v = Wxo[k * HID + j];
            else if (k < KA)     v = Who[(k - IN_DIM) * HID + j];
        }
        g_W[idx] = v;
    }
}

__global__ void bias_kernel(const float* __restrict__ bvec, const float* __restrict__ bo) {
    int n = blockIdx.x * blockDim.x + threadIdx.x;
    if (n >= NB) return;
    if (n < PARTS * GATES3) g_bias[n] = bvec[(n / GATES3) * GATES3 + (n % GATES3)];
    else                    g_bias[n] = bo[n - PARTS * GATES3];
}

// Zero c, build A for t=0 (h=0, pad=0, x_0 gathered).
__global__ void init_kernel(const float* __restrict__ x) {
    int idx = blockIdx.x * blockDim.x + threadIdx.x;
    const int nA = BATCH * KP;
    const int total = nA + BATCH * PARTS * HID;
    for (; idx < total; idx += gridDim.x * blockDim.x) {
        if (idx < nA) {
            int b = idx / KP, k = idx % KP;
            float v = 0.0f;
            if (k < IN_DIM) {
                int p = k / DP, d = k % DP;
                v = x[((p * BATCH + b) * SEQ + 0) * DP + d];
            }
            g_A[idx] = v;
        } else {
            g_c[idx - nA] = 0.0f;
        }
    }
}

// ---------------------------------------------------------------------------
// Step GEMM: G[128, 8192] = A[128, 672] @ W[672, 8192] + bias
// One block per 64-column stripe (grid = 128). 256 threads, 8x4 per thread.
// ---------------------------------------------------------------------------
__global__ void __launch_bounds__(256) gemm_kernel() {
    __shared__ float As[BK][BATCH];
    __shared__ float Bs[BK][BN];

    const int tid = threadIdx.x;
    const int n0  = blockIdx.x * BN;
    const int tr  = tid >> 4;   // 0..15  (row group, TM=8 -> covers 128)
    const int tc  = tid & 15;   // 0..15  (col group, TN=4 -> covers 64)

    float acc[TM][TN];
#pragma unroll
    for (int i = 0; i < TM; i++)
#pragma unroll
        for (int j = 0; j < TN; j++) acc[i][j] = 0.0f;

    // B-tile load indices (reused each iter)
    const int brow = tid >> 4;   // 0..15
    const int bc4  = tid & 15;   // 0..15 -> float4 column

    for (int k0 = 0; k0 < KP; k0 += BK) {
        // A tile 128x16 = 512 float4; 2 per thread, store transposed
#pragma unroll
        for (int l = 0; l < 2; l++) {
            int idx = tid + l * 256;
            int row = idx >> 2;
            int kq  = idx & 3;
            float4 v = *reinterpret_cast<const float4*>(&g_A[row * KP + k0 + kq * 4]);
            As[kq * 4 + 0][row] = v.x;
            As[kq * 4 + 1][row] = v.y;
            As[kq * 4 + 2][row] = v.z;
            As[kq * 4 + 3][row] = v.w;
        }
        // B tile 16x64 = 256 float4; 1 per thread
        {
            float4 v = *reinterpret_cast<const float4*>(&g_W[(k0 + brow) * NB + n0 + bc4 * 4]);
            *reinterpret_cast<float4*>(&Bs[brow][bc4 * 4]) = v;
        }
        __syncthreads();

#pragma unroll
        for (int kk = 0; kk < BK; kk++) {
            float a[TM], bb[TN];
#pragma unroll
            for (int i = 0; i < TM; i++) a[i] = As[kk][tr * TM + i];
#pragma unroll
            for (int j = 0; j < TN; j++) bb[j] = Bs[kk][tc * TN + j];
#pragma unroll
            for (int i = 0; i < TM; i++)
#pragma unroll
                for (int j = 0; j < TN; j++) acc[i][j] += a[i] * bb[j];
        }
        __syncthreads();
    }

#pragma unroll
    for (int i = 0; i < TM; i++) {
        int row = tr * TM + i;
#pragma unroll
        for (int j = 0; j < TN; j++) {
            int col = n0 + tc * TN + j;
            g_G[row * NB + col] = acc[i][j] + g_bias[col];
        }
    }
}

// ---------------------------------------------------------------------------
// Cell update: c_new = sig(f)*c + sig(i)*tanh(g); h = sig(o)*tanh(sum_p c_new)
// Writes h into A, gathers x_{t+1} into A. grid=(BATCH), block=(HID).
// ---------------------------------------------------------------------------
__global__ void cell_kernel(const float* __restrict__ x, int t) {
    const int b  = blockIdx.x;
    const int hh = threadIdx.x;
    const float* Gr = g_G + b * NB;

    float csum = 0.0f;
#pragma unroll
    for (int p = 0; p < PARTS; p++) {
        float iv = Gr[p * GATES3 + hh];
        float fv = Gr[p * GATES3 + HID + hh];
        float gv = Gr[p * GATES3 + 2 * HID + hh];
        float co = g_c[(b * PARTS + p) * HID + hh];
        float cn = sigf(fv) * co + sigf(iv) * tanhf(gv);
        g_c[(b * PARTS + p) * HID + hh] = cn;
        csum += cn;
    }
    float o = sigf(Gr[PARTS * GATES3 + hh]);
    g_A[b * KP + IN_DIM + hh] = o * tanhf(csum);

    if (hh < IN_DIM && t + 1 < SEQ) {
        int p = hh / DP, d = hh % DP;
        g_A[b * KP + hh] = x[((p * BATCH + b) * SEQ + (t + 1)) * DP + d];
    }
}

// ---------------------------------------------------------------------------
// Classifier + log_softmax. grid=(BATCH), block=(64).
// ---------------------------------------------------------------------------
__global__ void head_kernel(const float* __restrict__ fc_w, const float* __restrict__ fc_b,
                            float* __restrict__ out) {
    __shared__ float logits[CLASSES];
    const int b = blockIdx.x;
    const int c = threadIdx.x;
    if (c < CLASSES) {
        float acc = fc_b[c];
        const float* h = g_A + b * KP + IN_DIM;
        for (int k = 0; k < HID; k++) acc += h[k] * fc_w[k * CLASSES + c];
        logits[c] = acc;
    }
    __syncthreads();
    if (c < CLASSES) {
        float m = -1e30f;
        for (int j = 0; j < CLASSES; j++) m = fmaxf(m, logits[j]);
        float s = 0.0f;
        for (int j = 0; j < CLASSES; j++) s += expf(logits[j] - m);
        out[b * CLASSES + c] = logits[c] - m - logf(s);
    }
}

extern "C" void kernel_launch(void* const* d_in, const int* in_sizes, int n_in,
                              void* d_out, int out_size) {
    const float* inputs = (const float*)d_in[0];
    const float* Wx     = (const float*)d_in[1];
    const float* Wh     = (const float*)d_in[2];
    const float* bvec   = (const float*)d_in[3];
    const float* Wxo    = (const float*)d_in[4];
    const float* Who    = (const float*)d_in[5];
    const float* bo     = (const float*)d_in[6];
    const float* fc_w   = (const float*)d_in[7];
    const float* fc_b   = (const float*)d_in[8];
    float* out = (float*)d_out;

    pack_kernel<<<2048, 256>>>(Wx, Wh, Wxo, Who);
    bias_kernel<<<(NB + 255) / 256, 256>>>(bvec, bo);
    init_kernel<<<512, 256>>>(inputs);

    for (int t = 0; t < SEQ; t++) {
        gemm_kernel<<<NB / BN, 256>>>();
        cell_kernel<<<BATCH, HID>>>(inputs, t);
    }

    head_kernel<<<BATCH, 64>>>(fc_w, fc_b, out);
}

// round 9
// speedup vs baseline: 1.7845x; 1.7845x over previous
#include <cuda_runtime.h>
#include <math.h>
#include <stdint.h>

// Problem constants
#define PARTS   5
#define BATCH   128
#define SEQ     300
#define DP      30
#define HID     512
#define CLASSES 60
#define IN_DIM  150
#define GATES3  1536
#define NB      8192          // 5*1536 gate cols + 512 o_pre cols
#define KA      662           // 150 + 512
#define KP      672           // padded to 84*8
#define NK8     84            // k8 slices
#define NCHUNK  21            // K chunks of 32 (4 k8 each)

// ---- device globals (no allocation allowed) --------------------------------
// A operand (activations) fragment-major: [k8 0..83][mi 0..7][lane 0..31][4]
__device__ float g_Ahi[KP * BATCH];
__device__ float g_Alo[KP * BATCH];
// B operand (weights) fragment-major: [nblk 0..63][k8 0..83][ni 0..15][lane][2]
__device__ float g_Wt_hi[KP * NB];   // 22 MB
__device__ float g_Wt_lo[KP * NB];   // 22 MB
__device__ float g_bias[NB];
__device__ float g_h[BATCH * HID];
__device__ float g_G[BATCH * NB];            // [b][n] gate pre-activations
__device__ float g_c[BATCH * PARTS * HID];

__device__ __forceinline__ float sigf(float x) { return 1.0f / (1.0f + expf(-x)); }
__device__ __forceinline__ float to_tf32(float x) {
    float r; asm("cvt.rna.tf32.f32 %0, %1;" : "=f"(r) : "f"(x)); return r;
}
__device__ __forceinline__ uint32_t smem_u32(const void* p) {
    uint32_t a;
    asm("{ .reg .u64 t; cvta.to.shared.u64 t, %1; cvt.u32.u64 %0, t; }" : "=r"(a) : "l"(p));
    return a;
}

// Write fp32 value v (split hi/lo tf32) at logical A position (batch b, k).
// Fragment map for mma.m16n8k8 A (row-major 16x8): lane g*4+t holds
// j0:(g,t) j1:(g+8,t) j2:(g,t+4) j3:(g+8,t+4)
__device__ __forceinline__ void write_A(int b, int k, float v) {
    int kc = k >> 3, c = k & 7;
    int mi = b >> 4, r = b & 15;
    int g = r & 7, t = c & 3;
    int lane = g * 4 + t;
    int j = (r >> 3) + 2 * (c >> 2);
    int off = ((kc * 8 + mi) * 32 + lane) * 4 + j;
    float hi = to_tf32(v);
    g_Ahi[off] = hi;
    g_Alo[off] = to_tf32(v - hi);
}

// ---------------------------------------------------------------------------
// Pack weights: logical W[k][n] (same map as passing R4 kernel) into the
// B-fragment-major split layout. B fragment (col-major 8x8 k x n): lane g*4+t
// holds b0:(k=t, n=g) b1:(k=t+4, n=g).
// ---------------------------------------------------------------------------
__global__ void pack_kernel(const float* __restrict__ Wx, const float* __restrict__ Wh,
                            const float* __restrict__ Wxo, const float* __restrict__ Who) {
    int idx = blockIdx.x * blockDim.x + threadIdx.x;
    const int total = KP * NB;
    for (; idx < total; idx += gridDim.x * blockDim.x) {
        int k = idx / NB, n = idx % NB;
        float v = 0.0f;
        if (n < PARTS * GATES3) {
            int p = n / GATES3, gi = n % GATES3;
            if (k < IN_DIM) {
                if (k >= p * DP && k < p * DP + DP) v = Wx[k * GATES3 + gi];
            } else if (k < KA) {
                v = Wh[(p * HID + (k - IN_DIM)) * GATES3 + gi];
            }
        } else {
            int j = n - PARTS * GATES3;
            if (k < IN_DIM)   v = Wxo[k * HID + j];
            else if (k < KA)  v = Who[(k - IN_DIM) * HID + j];
        }
        int nblk = n >> 7, nn = n & 127;
        int ni = nn >> 3, g = nn & 7;
        int kc = k >> 3, c = k & 7;
        int tig = c & 3, half = c >> 2;
        int lane = g * 4 + tig;
        size_t off = ((size_t)((nblk * NK8 + kc) * 16 + ni) * 32 + lane) * 2 + half;
        float hi = to_tf32(v);
        g_Wt_hi[off] = hi;
        g_Wt_lo[off] = to_tf32(v - hi);
    }
}

__global__ void bias_kernel(const float* __restrict__ bvec, const float* __restrict__ bo) {
    int n = blockIdx.x * blockDim.x + threadIdx.x;
    if (n >= NB) return;
    if (n < PARTS * GATES3) g_bias[n] = bvec[(n / GATES3) * GATES3 + (n % GATES3)];
    else                    g_bias[n] = bo[n - PARTS * GATES3];
}

// A(t=0): x_0 in k<150, zeros elsewhere (h=0, pad=0). Zero c.
__global__ void init_kernel(const float* __restrict__ x) {
    int idx = blockIdx.x * blockDim.x + threadIdx.x;
    const int nA = BATCH * KP;
    const int total = nA + BATCH * PARTS * HID;
    for (; idx < total; idx += gridDim.x * blockDim.x) {
        if (idx < nA) {
            int b = idx / KP, k = idx % KP;
            float v = 0.0f;
            if (k < IN_DIM) {
                int p = k / DP, d = k % DP;
                v = x[((p * BATCH + b) * SEQ + 0) * DP + d];
            }
            write_A(b, k, v);
        } else {
            g_c[idx - nA] = 0.0f;
        }
    }
}

// ---------------------------------------------------------------------------
// Step GEMM: G[128,8192] = A[128,672] @ W[672,8192] + bias  (3x tf32 mma.sync)
// grid = (64 n-blocks, 2 m-blocks); 256 threads; 64x128 block tile;
// 8 warps -> 32x32 warp tiles; BK=32; double-buffered cp.async.
// ---------------------------------------------------------------------------
__device__ __forceinline__ void mma8(float* d, const float4& a, const float2& b) {
    asm volatile(
        "mma.sync.aligned.m16n8k8.row.col.f32.tf32.tf32.f32 "
        "{%0,%1,%2,%3}, {%4,%5,%6,%7}, {%8,%9}, {%0,%1,%2,%3};"
        : "+f"(d[0]), "+f"(d[1]), "+f"(d[2]), "+f"(d[3])
        : "r"(__float_as_uint(a.x)), "r"(__float_as_uint(a.y)),
          "r"(__float_as_uint(a.z)), "r"(__float_as_uint(a.w)),
          "r"(__float_as_uint(b.x)), "r"(__float_as_uint(b.y)));
}
__device__ __forceinline__ void cp16(float* smem_dst, const float* gsrc) {
    uint32_t d = smem_u32(smem_dst);
    unsigned long long g = (unsigned long long)__cvta_generic_to_global(gsrc);
    asm volatile("cp.async.cg.shared.global [%0], [%1], 16;" :: "r"(d), "l"(g));
}

// stage layout (floats): Ahi[2048] Alo[2048] Bhi[4096] Blo[4096] = 12288 (48KB)
#define STAGE_F 12288

__device__ __forceinline__ void fill_stage(float* st, int j, int mb, int nblk, int tid) {
    // A: [kcl 0..3][mi_l 0..3][lane][4]; global [k8][mi(8)][lane][4]
    for (int i = tid; i < 512; i += 256) {
        int kcl = i >> 7, rem = i & 127;
        int mi_l = rem >> 5, lane = rem & 31;
        int gidx = (((j * 4 + kcl) * 8 + mb * 4 + mi_l) * 32 + lane) * 4;
        cp16(st + i * 4,        g_Ahi + gidx);
        cp16(st + 2048 + i * 4, g_Alo + gidx);
    }
    // B: contiguous 4096-float slice per split
    size_t gb = (size_t)(nblk * NK8 + j * 4) * 1024;
    for (int i = tid; i < 1024; i += 256) {
        cp16(st + 4096 + i * 4, g_Wt_hi + gb + i * 4);
        cp16(st + 8192 + i * 4, g_Wt_lo + gb + i * 4);
    }
    asm volatile("cp.async.commit_group;");
}

__global__ void __launch_bounds__(256) gemm_kernel() {
    extern __shared__ float sm[];
    const int tid  = threadIdx.x;
    const int wid  = tid >> 5;
    const int lane = tid & 31;
    const int wm   = wid & 1;      // 2 m-warps
    const int wn   = wid >> 1;     // 4 n-warps
    const int nblk = blockIdx.x;   // 0..63
    const int mb   = blockIdx.y;   // 0..1

    float acc[2][4][4];
#pragma unroll
    for (int ms = 0; ms < 2; ms++)
#pragma unroll
        for (int ns = 0; ns < 4; ns++)
#pragma unroll
            for (int q = 0; q < 4; q++) acc[ms][ns][q] = 0.0f;

    fill_stage(sm, 0, mb, nblk, tid);

    for (int j = 0; j < NCHUNK; j++) {
        if (j + 1 < NCHUNK) {
            fill_stage(sm + ((j + 1) & 1) * STAGE_F, j + 1, mb, nblk, tid);
            asm volatile("cp.async.wait_group 1;");
        } else {
            asm volatile("cp.async.wait_group 0;");
        }
        __syncthreads();

        const float* st = sm + (j & 1) * STAGE_F;
        const float* Ah = st;
        const float* Al = st + 2048;
        const float* Bh = st + 4096;
        const float* Bl = st + 8192;

#pragma unroll
        for (int kcl = 0; kcl < 4; kcl++) {
            float4 ah[2], al[2];
#pragma unroll
            for (int ms = 0; ms < 2; ms++) {
                int fi = ((kcl * 4 + wm * 2 + ms) * 32 + lane) * 4;
                ah[ms] = *(const float4*)(Ah + fi);
                al[ms] = *(const float4*)(Al + fi);
            }
            float2 bh[4], bl[4];
#pragma unroll
            for (int ns = 0; ns < 4; ns++) {
                int gi = ((kcl * 16 + wn * 4 + ns) * 32 + lane) * 2;
                bh[ns] = *(const float2*)(Bh + gi);
                bl[ns] = *(const float2*)(Bl + gi);
            }
#pragma unroll
            for (int ms = 0; ms < 2; ms++)
#pragma unroll
                for (int ns = 0; ns < 4; ns++) {
                    mma8(acc[ms][ns], ah[ms], bh[ns]);
                    mma8(acc[ms][ns], ah[ms], bl[ns]);
                    mma8(acc[ms][ns], al[ms], bh[ns]);
                }
        }
        __syncthreads();
    }

    // epilogue: D tile map c0:(g,2t) c1:(g,2t+1) c2:(g+8,2t) c3:(g+8,2t+1)
    const int g = lane >> 2, t = lane & 3;
#pragma unroll
    for (int ms = 0; ms < 2; ms++) {
        int m0 = mb * 64 + wm * 32 + ms * 16;
#pragma unroll
        for (int ns = 0; ns < 4; ns++) {
            int col = nblk * 128 + wn * 32 + ns * 8 + 2 * t;
            float2 bv = *(const float2*)&g_bias[col];
            float2 v0 = { acc[ms][ns][0] + bv.x, acc[ms][ns][1] + bv.y };
            float2 v1 = { acc[ms][ns][2] + bv.x, acc[ms][ns][3] + bv.y };
            *(float2*)&g_G[(size_t)(m0 + g)     * NB + col] = v0;
            *(float2*)&g_G[(size_t)(m0 + g + 8) * NB + col] = v1;
        }
    }
}

// ---------------------------------------------------------------------------
// Cell update. grid=(BATCH), block=(HID). Writes h (fragment layout into A,
// plain into g_h) and gathers x_{t+1} into A.
// ---------------------------------------------------------------------------
__global__ void cell_kernel(const float* __restrict__ x, int t) {
    const int b  = blockIdx.x;
    const int hh = threadIdx.x;
    const float* Gr = g_G + (size_t)b * NB;

    float csum = 0.0f;
#pragma unroll
    for (int p = 0; p < PARTS; p++) {
        float iv = Gr[p * GATES3 + hh];
        float fv = Gr[p * GATES3 + HID + hh];
        float gv = Gr[p * GATES3 + 2 * HID + hh];
        float co = g_c[(b * PARTS + p) * HID + hh];
        float cn = sigf(fv) * co + sigf(iv) * tanhf(gv);
        g_c[(b * PARTS + p) * HID + hh] = cn;
        csum += cn;
    }
    float o  = sigf(Gr[PARTS * GATES3 + hh]);
    float hv = o * tanhf(csum);
    g_h[b * HID + hh] = hv;
    write_A(b, IN_DIM + hh, hv);

    if (hh < IN_DIM && t + 1 < SEQ) {
        int p = hh / DP, d = hh % DP;
        write_A(b, hh, x[((p * BATCH + b) * SEQ + (t + 1)) * DP + d]);
    }
}

// ---------------------------------------------------------------------------
// Classifier + log_softmax. grid=(BATCH), block=(64).
// ---------------------------------------------------------------------------
__global__ void head_kernel(const float* __restrict__ fc_w, const float* __restrict__ fc_b,
                            float* __restrict__ out) {
    __shared__ float logits[CLASSES];
    const int b = blockIdx.x;
    const int c = threadIdx.x;
    if (c < CLASSES) {
        float acc = fc_b[c];
        const float* h = g_h + b * HID;
        for (int k = 0; k < HID; k++) acc += h[k] * fc_w[k * CLASSES + c];
        logits[c] = acc;
    }
    __syncthreads();
    if (c < CLASSES) {
        float m = -1e30f;
        for (int j = 0; j < CLASSES; j++) m = fmaxf(m, logits[j]);
        float s = 0.0f;
        for (int j = 0; j < CLASSES; j++) s += expf(logits[j] - m);
        out[b * CLASSES + c] = logits[c] - m - logf(s);
    }
}

extern "C" void kernel_launch(void* const* d_in, const int* in_sizes, int n_in,
                              void* d_out, int out_size) {
    const float* inputs = (const float*)d_in[0];
    const float* Wx     = (const float*)d_in[1];
    const float* Wh     = (const float*)d_in[2];
    const float* bvec   = (const float*)d_in[3];
    const float* Wxo    = (const float*)d_in[4];
    const float* Who    = (const float*)d_in[5];
    const float* bo     = (const float*)d_in[6];
    const float* fc_w   = (const float*)d_in[7];
    const float* fc_b   = (const float*)d_in[8];
    float* out = (float*)d_out;

    static int smem_set = 0;
    if (!smem_set) {
        cudaFuncSetAttribute(gemm_kernel, cudaFuncAttributeMaxDynamicSharedMemorySize,
                             2 * STAGE_F * sizeof(float));
        smem_set = 1;
    }

    pack_kernel<<<2048, 256>>>(Wx, Wh, Wxo, Who);
    bias_kernel<<<(NB + 255) / 256, 256>>>(bvec, bo);
    init_kernel<<<512, 256>>>(inputs);

    dim3 ggrid(64, 2);
    for (int t = 0; t < SEQ; t++) {
        gemm_kernel<<<ggrid, 256, 2 * STAGE_F * sizeof(float)>>>();
        cell_kernel<<<BATCH, HID>>>(inputs, t);
    }

    head_kernel<<<BATCH, 64>>>(fc_w, fc_b, out);
}

// round 10
// speedup vs baseline: 2.7761x; 1.5557x over previous
#include <cuda_runtime.h>
#include <cuda_bf16.h>
#include <math.h>
#include <stdint.h>

// Problem constants
#define PARTS   5
#define BATCH   128
#define SEQ     300
#define DP      30
#define HID     512
#define CLASSES 60
#define IN_DIM  150
#define GATES3  1536
#define NB      8192          // 5*1536 gate cols + 512 o_pre cols
#define KA      662           // 150 + 512
#define KP      672           // padded; 42 k16 slices
#define NK16    42
#define NCHUNK  21            // K chunks of 32 (2 k16 slices each)

// ---- device globals (no allocation allowed) --------------------------------
// A operand fragment-major (bf16): [k16 0..41][mi 0..7][lane 0..31][4 regs x 2]
__device__ __nv_bfloat16 g_Abf_hi[KP * BATCH];
__device__ __nv_bfloat16 g_Abf_lo[KP * BATCH];
// B operand fragment-major (bf16): [nblk 0..63][k16][ni 0..15][lane][2 regs x 2]
__device__ __nv_bfloat16 g_Wb_hi[(size_t)KP * NB];   // 11 MB
__device__ __nv_bfloat16 g_Wb_lo[(size_t)KP * NB];   // 11 MB
__device__ float g_bias[NB];
__device__ float g_h[BATCH * HID];
__device__ float g_G[BATCH * NB];
__device__ float g_c[BATCH * PARTS * HID];

__device__ __forceinline__ float sigf(float x) { return 1.0f / (1.0f + expf(-x)); }
__device__ __forceinline__ uint32_t smem_u32(const void* p) {
    uint32_t a;
    asm("{ .reg .u64 t; cvta.to.shared.u64 t, %1; cvt.u32.u64 %0, t; }" : "=r"(a) : "l"(p));
    return a;
}

// Write fp32 v (split hi/lo bf16) at logical A position (batch b, k).
// m16n8k16 A frag (16x16 row-major): lane g*4+t; a0:(g,2t),(g,2t+1)
// a1:(g+8,2t..) a2:(g,2t+8..) a3:(g+8,2t+8..); low half = even k.
__device__ __forceinline__ void write_A(int b, int k, float v) {
    int k16 = k >> 4, c = k & 15;
    int mi = b >> 4, r = b & 15;
    int g = r & 7, t = (c & 7) >> 1;
    int lane = g * 4 + t;
    int reg = (r >> 3) + 2 * (c >> 3);
    int half = c & 1;
    int idx = (((k16 * 8 + mi) * 32 + lane) * 4 + reg) * 2 + half;
    __nv_bfloat16 hi = __float2bfloat16_rn(v);
    g_Abf_hi[idx] = hi;
    g_Abf_lo[idx] = __float2bfloat16_rn(v - __bfloat162float(hi));
}

// ---------------------------------------------------------------------------
// Pack weights: logical W[k][n] (same map as passing R4/R9 kernels) into
// B-fragment-major split layout. m16n8k16 B frag (16k x 8n col): lane g*4+t;
// b0:(2t,g),(2t+1,g)  b1:(2t+8,g),(2t+9,g).
// ---------------------------------------------------------------------------
__global__ void pack_kernel(const float* __restrict__ Wx, const float* __restrict__ Wh,
                            const float* __restrict__ Wxo, const float* __restrict__ Who) {
    size_t idx = blockIdx.x * (size_t)blockDim.x + threadIdx.x;
    const size_t total = (size_t)KP * NB;
    for (; idx < total; idx += gridDim.x * (size_t)blockDim.x) {
        int k = (int)(idx / NB), n = (int)(idx % NB);
        float v = 0.0f;
        if (n < PARTS * GATES3) {
            int p = n / GATES3, gi = n % GATES3;
            if (k < IN_DIM) {
                if (k >= p * DP && k < p * DP + DP) v = Wx[k * GATES3 + gi];
            } else if (k < KA) {
                v = Wh[(p * HID + (k - IN_DIM)) * GATES3 + gi];
            }
        } else {
            int j = n - PARTS * GATES3;
            if (k < IN_DIM)   v = Wxo[k * HID + j];
            else if (k < KA)  v = Who[(k - IN_DIM) * HID + j];
        }
        int nblk = n >> 7, nn = n & 127;
        int ni = nn >> 3, g = nn & 7;
        int k16 = k >> 4, c = k & 15;
        int t = (c & 7) >> 1, half = c & 1, reg = c >> 3;
        int lane = g * 4 + t;
        size_t off = (((size_t)(nblk * NK16 + k16) * 16 + ni) * 32 + lane) * 4
                   + reg * 2 + half;
        __nv_bfloat16 hi = __float2bfloat16_rn(v);
        g_Wb_hi[off] = hi;
        g_Wb_lo[off] = __float2bfloat16_rn(v - __bfloat162float(hi));
    }
}

__global__ void bias_kernel(const float* __restrict__ bvec, const float* __restrict__ bo) {
    int n = blockIdx.x * blockDim.x + threadIdx.x;
    if (n >= NB) return;
    if (n < PARTS * GATES3) g_bias[n] = bvec[(n / GATES3) * GATES3 + (n % GATES3)];
    else                    g_bias[n] = bo[n - PARTS * GATES3];
}

// A(t=0): x_0 in k<150, zeros elsewhere. Zero c.
__global__ void init_kernel(const float* __restrict__ x) {
    int idx = blockIdx.x * blockDim.x + threadIdx.x;
    const int nA = BATCH * KP;
    const int total = nA + BATCH * PARTS * HID;
    for (; idx < total; idx += gridDim.x * blockDim.x) {
        if (idx < nA) {
            int b = idx / KP, k = idx % KP;
            float v = 0.0f;
            if (k < IN_DIM) {
                int p = k / DP, d = k % DP;
                v = x[((p * BATCH + b) * SEQ + 0) * DP + d];
            }
            write_A(b, k, v);
        } else {
            g_c[idx - nA] = 0.0f;
        }
    }
}

// ---------------------------------------------------------------------------
// Step GEMM: G[128,8192] = A[128,672] @ W[672,8192] + bias
// 2-way bf16 split x mma.m16n8k16 (3 mma per combo-set).
// grid = (64 n-blocks, 2 m-blocks); 256 thr; 64x128 tile; warps 32x32;
// BK=32 (2 k16 slices); 3-stage cp.async pipeline, 1 sync per chunk.
// ---------------------------------------------------------------------------
__device__ __forceinline__ void mma16(float* d, const uint4& a, const uint2& b) {
    asm volatile(
        "mma.sync.aligned.m16n8k16.row.col.f32.bf16.bf16.f32 "
        "{%0,%1,%2,%3}, {%4,%5,%6,%7}, {%8,%9}, {%0,%1,%2,%3};"
        : "+f"(d[0]), "+f"(d[1]), "+f"(d[2]), "+f"(d[3])
        : "r"(a.x), "r"(a.y), "r"(a.z), "r"(a.w), "r"(b.x), "r"(b.y));
}
__device__ __forceinline__ void cp16(uint32_t* smem_dst, const void* gsrc) {
    uint32_t d = smem_u32(smem_dst);
    unsigned long long g = (unsigned long long)__cvta_generic_to_global(gsrc);
    asm volatile("cp.async.cg.shared.global [%0], [%1], 16;" :: "r"(d), "l"(g));
}

// stage layout (u32): Ah[0..1024) Al[1024..2048) Bh[2048..4096) Bl[4096..6144)
#define STAGE_U 6144          // 24 KB
#define NSTAGE  3

__device__ __forceinline__ void fill_stage(uint32_t* st, int j, int mb, int nblk,
                                           int tid) {
    const uint32_t* gAh = (const uint32_t*)g_Abf_hi;
    const uint32_t* gAl = (const uint32_t*)g_Abf_lo;
    const uint32_t* gBh = (const uint32_t*)g_Wb_hi;
    const uint32_t* gBl = (const uint32_t*)g_Wb_lo;
    // A: 2 slices x 4 mi x 32 lanes, 16B per lane (hi and lo)
    {
        int i = tid;                       // 256 transfers, exactly one per thread
        int slice = i >> 7, rem = i & 127;
        int mi_l = rem >> 5, lane = rem & 31;
        int gidx = (((j * 2 + slice) * 8 + mb * 4 + mi_l) * 32 + lane) * 4;
        int soff = slice * 512 + mi_l * 128 + lane * 4;
        cp16(st + soff,        gAh + gidx);
        cp16(st + 1024 + soff, gAl + gidx);
    }
    // B: 2 slices x 1024 u32 contiguous per split
#pragma unroll
    for (int i = tid; i < 512; i += 256) {
        int slice = i >> 8, rem = i & 255;
        size_t gidx = ((size_t)(nblk * NK16 + j * 2 + slice)) * 1024 + rem * 4;
        int soff = slice * 1024 + rem * 4;
        cp16(st + 2048 + soff, gBh + gidx);
        cp16(st + 4096 + soff, gBl + gidx);
    }
    asm volatile("cp.async.commit_group;");
}

__global__ void __launch_bounds__(256) gemm_kernel() {
    extern __shared__ uint32_t sm[];
    const int tid  = threadIdx.x;
    const int wid  = tid >> 5;
    const int lane = tid & 31;
    const int wm   = wid & 1;
    const int wn   = wid >> 1;
    const int nblk = blockIdx.x;
    const int mb   = blockIdx.y;

    float acc[2][4][4];
#pragma unroll
    for (int ms = 0; ms < 2; ms++)
#pragma unroll
        for (int ns = 0; ns < 4; ns++)
#pragma unroll
            for (int q = 0; q < 4; q++) acc[ms][ns][q] = 0.0f;

    fill_stage(sm, 0, mb, nblk, tid);
    fill_stage(sm + STAGE_U, 1, mb, nblk, tid);

    for (int j = 0; j < NCHUNK; j++) {
        if (j < NCHUNK - 1) asm volatile("cp.async.wait_group 1;");
        else                asm volatile("cp.async.wait_group 0;");
        __syncthreads();

        if (j + 2 < NCHUNK)
            fill_stage(sm + ((j + 2) % NSTAGE) * STAGE_U, j + 2, mb, nblk, tid);

        const uint32_t* st = sm + (j % NSTAGE) * STAGE_U;
#pragma unroll
        for (int slice = 0; slice < 2; slice++) {
            uint4 ah[2], al[2];
#pragma unroll
            for (int ms = 0; ms < 2; ms++) {
                int fi = slice * 512 + (wm * 2 + ms) * 128 + lane * 4;
                ah[ms] = *(const uint4*)(st + fi);
                al[ms] = *(const uint4*)(st + 1024 + fi);
            }
            uint2 bh[4], bl[4];
#pragma unroll
            for (int ns = 0; ns < 4; ns++) {
                int gi = slice * 1024 + (wn * 4 + ns) * 64 + lane * 2;
                bh[ns] = *(const uint2*)(st + 2048 + gi);
                bl[ns] = *(const uint2*)(st + 4096 + gi);
            }
#pragma unroll
            for (int ms = 0; ms < 2; ms++)
#pragma unroll
                for (int ns = 0; ns < 4; ns++) {
                    mma16(acc[ms][ns], ah[ms], bh[ns]);
                    mma16(acc[ms][ns], ah[ms], bl[ns]);
                    mma16(acc[ms][ns], al[ms], bh[ns]);
                }
        }
    }

    // epilogue: D map c0:(g,2t) c1:(g,2t+1) c2:(g+8,2t) c3:(g+8,2t+1)
    const int g = lane >> 2, t = lane & 3;
#pragma unroll
    for (int ms = 0; ms < 2; ms++) {
        int m0 = mb * 64 + wm * 32 + ms * 16;
#pragma unroll
        for (int ns = 0; ns < 4; ns++) {
            int col = nblk * 128 + wn * 32 + ns * 8 + 2 * t;
            float2 bv = *(const float2*)&g_bias[col];
            float2 v0 = { acc[ms][ns][0] + bv.x, acc[ms][ns][1] + bv.y };
            float2 v1 = { acc[ms][ns][2] + bv.x, acc[ms][ns][3] + bv.y };
            *(float2*)&g_G[(size_t)(m0 + g)     * NB + col] = v0;
            *(float2*)&g_G[(size_t)(m0 + g + 8) * NB + col] = v1;
        }
    }
}

// ---------------------------------------------------------------------------
// Cell update. grid=(BATCH), block=(HID).
// ---------------------------------------------------------------------------
__global__ void cell_kernel(const float* __restrict__ x, int t) {
    const int b  = blockIdx.x;
    const int hh = threadIdx.x;
    const float* Gr = g_G + (size_t)b * NB;

    float csum = 0.0f;
#pragma unroll
    for (int p = 0; p < PARTS; p++) {
        float iv = Gr[p * GATES3 + hh];
        float fv = Gr[p * GATES3 + HID + hh];
        float gv = Gr[p * GATES3 + 2 * HID + hh];
        float co = g_c[(b * PARTS + p) * HID + hh];
        float cn = sigf(fv) * co + sigf(iv) * tanhf(gv);
        g_c[(b * PARTS + p) * HID + hh] = cn;
        csum += cn;
    }
    float o  = sigf(Gr[PARTS * GATES3 + hh]);
    float hv = o * tanhf(csum);
    g_h[b * HID + hh] = hv;
    write_A(b, IN_DIM + hh, hv);

    if (hh < IN_DIM && t + 1 < SEQ) {
        int p = hh / DP, d = hh % DP;
        write_A(b, hh, x[((p * BATCH + b) * SEQ + (t + 1)) * DP + d]);
    }
}

// ---------------------------------------------------------------------------
// Classifier + log_softmax. grid=(BATCH), block=(64).
// ---------------------------------------------------------------------------
__global__ void head_kernel(const float* __restrict__ fc_w, const float* __restrict__ fc_b,
                            float* __restrict__ out) {
    __shared__ float logits[CLASSES];
    const int b = blockIdx.x;
    const int c = threadIdx.x;
    if (c < CLASSES) {
        float acc = fc_b[c];
        const float* h = g_h + b * HID;
        for (int k = 0; k < HID; k++) acc += h[k] * fc_w[k * CLASSES + c];
        logits[c] = acc;
    }
    __syncthreads();
    if (c < CLASSES) {
        float m = -1e30f;
        for (int j = 0; j < CLASSES; j++) m = fmaxf(m, logits[j]);
        float s = 0.0f;
        for (int j = 0; j < CLASSES; j++) s += expf(logits[j] - m);
        out[b * CLASSES + c] = logits[c] - m - logf(s);
    }
}

extern "C" void kernel_launch(void* const* d_in, const int* in_sizes, int n_in,
                              void* d_out, int out_size) {
    const float* inputs = (const float*)d_in[0];
    const float* Wx     = (const float*)d_in[1];
    const float* Wh     = (const float*)d_in[2];
    const float* bvec   = (const float*)d_in[3];
    const float* Wxo    = (const float*)d_in[4];
    const float* Who    = (const float*)d_in[5];
    const float* bo     = (const float*)d_in[6];
    const float* fc_w   = (const float*)d_in[7];
    const float* fc_b   = (const float*)d_in[8];
    float* out = (float*)d_out;

    static int smem_set = 0;
    if (!smem_set) {
        cudaFuncSetAttribute(gemm_kernel, cudaFuncAttributeMaxDynamicSharedMemorySize,
                             NSTAGE * STAGE_U * sizeof(uint32_t));
        smem_set = 1;
    }

    pack_kernel<<<2048, 256>>>(Wx, Wh, Wxo, Who);
    bias_kernel<<<(NB + 255) / 256, 256>>>(bvec, bo);
    init_kernel<<<512, 256>>>(inputs);

    dim3 ggrid(64, 2);
    for (int t = 0; t < SEQ; t++) {
        gemm_kernel<<<ggrid, 256, NSTAGE * STAGE_U * sizeof(uint32_t)>>>();
        cell_kernel<<<BATCH, HID>>>(inputs, t);
    }

    head_kernel<<<BATCH, 64>>>(fc_w, fc_b, out);
}

// round 11
// speedup vs baseline: 2.8411x; 1.0234x over previous
#include <cuda_runtime.h>
#include <cuda_bf16.h>
#include <math.h>
#include <stdint.h>

// Problem constants
#define PARTS   5
#define BATCH   128
#define SEQ     300
#define DP      30
#define HID     512
#define CLASSES 60
#define IN_DIM  150
#define GATES3  1536
#define NB      8192          // 5*1536 gate cols + 512 o_pre cols
// K layout (new): part p x-inputs at k in [32p, 32p+30), pad to 32;
// h at k in [160, 672). KP = 672 = 21 chunks of 32 = 42 k16 slices.
#define KP      672
#define NK16    42
#define NCHUNK  21
#define NCH_GATE 17           // gate n-blocks: 1 x chunk + 16 h chunks

// ---- device globals (no allocation allowed) --------------------------------
// A operand fragment-major (bf16): [k16 0..41][mi 0..7][lane 0..31][4 regs x 2]
__device__ __nv_bfloat16 g_Abf_hi[KP * BATCH];
__device__ __nv_bfloat16 g_Abf_lo[KP * BATCH];
// B operand fragment-major (bf16): [nblk 0..63][k16][ni 0..15][lane][2 regs x 2]
__device__ __nv_bfloat16 g_Wb_hi[(size_t)KP * NB];   // 11 MB
__device__ __nv_bfloat16 g_Wb_lo[(size_t)KP * NB];   // 11 MB
__device__ float g_bias[NB];
__device__ float g_h[BATCH * HID];
__device__ float g_G[BATCH * NB];
__device__ float g_c[BATCH * PARTS * HID];

__device__ __forceinline__ float sigf(float x) { return 1.0f / (1.0f + expf(-x)); }
__device__ __forceinline__ uint32_t smem_u32(const void* p) {
    uint32_t a;
    asm("{ .reg .u64 t; cvta.to.shared.u64 t, %1; cvt.u32.u64 %0, t; }" : "=r"(a) : "l"(p));
    return a;
}

// Write fp32 v (split hi/lo bf16) at logical A position (batch b, k).
// m16n8k16 A frag (16x16 row-major): lane g*4+t; a0:(g,2t),(g,2t+1)
// a1:(g+8,..) a2:(g,2t+8..) a3:(g+8,2t+8..).
__device__ __forceinline__ void write_A(int b, int k, float v) {
    int k16 = k >> 4, c = k & 15;
    int mi = b >> 4, r = b & 15;
    int g = r & 7, t = (c & 7) >> 1;
    int lane = g * 4 + t;
    int reg = (r >> 3) + 2 * (c >> 3);
    int half = c & 1;
    int idx = (((k16 * 8 + mi) * 32 + lane) * 4 + reg) * 2 + half;
    __nv_bfloat16 hi = __float2bfloat16_rn(v);
    g_Abf_hi[idx] = hi;
    g_Abf_lo[idx] = __float2bfloat16_rn(v - __bfloat162float(hi));
}

// ---------------------------------------------------------------------------
// Pack weights into B-fragment-major split layout with the NEW K map:
//   k < 160 : p = k>>5, d = k&31 (x input d of part p; d>=30 -> 0)
//   k >= 160: kh = k-160 (h input)
// Column map unchanged: n<7680 gate cols (part pc = n/1536), else o_pre.
// ---------------------------------------------------------------------------
__global__ void pack_kernel(const float* __restrict__ Wx, const float* __restrict__ Wh,
                            const float* __restrict__ Wxo, const float* __restrict__ Who) {
    size_t idx = blockIdx.x * (size_t)blockDim.x + threadIdx.x;
    const size_t total = (size_t)KP * NB;
    for (; idx < total; idx += gridDim.x * (size_t)blockDim.x) {
        int k = (int)(idx / NB), n = (int)(idx % NB);
        float v = 0.0f;
        if (n < PARTS * GATES3) {
            int pc = n / GATES3, gi = n % GATES3;
            if (k < 160) {
                int p = k >> 5, d = k & 31;
                if (p == pc && d < DP) v = Wx[(pc * DP + d) * GATES3 + gi];
            } else {
                v = Wh[(pc * HID + (k - 160)) * GATES3 + gi];
            }
        } else {
            int j = n - PARTS * GATES3;
            if (k < 160) {
                int p = k >> 5, d = k & 31;
                if (d < DP) v = Wxo[(p * DP + d) * HID + j];
            } else {
                v = Who[(k - 160) * HID + j];
            }
        }
        int nblk = n >> 7, nn = n & 127;
        int ni = nn >> 3, g = nn & 7;
        int k16 = k >> 4, c = k & 15;
        int t = (c & 7) >> 1, half = c & 1, reg = c >> 3;
        int lane = g * 4 + t;
        size_t off = (((size_t)(nblk * NK16 + k16) * 16 + ni) * 32 + lane) * 4
                   + reg * 2 + half;
        __nv_bfloat16 hi = __float2bfloat16_rn(v);
        g_Wb_hi[off] = hi;
        g_Wb_lo[off] = __float2bfloat16_rn(v - __bfloat162float(hi));
    }
}

__global__ void bias_kernel(const float* __restrict__ bvec, const float* __restrict__ bo) {
    int n = blockIdx.x * blockDim.x + threadIdx.x;
    if (n >= NB) return;
    if (n < PARTS * GATES3) g_bias[n] = bvec[(n / GATES3) * GATES3 + (n % GATES3)];
    else                    g_bias[n] = bo[n - PARTS * GATES3];
}

// A(t=0): x_0 at k<160 (per-part 32-aligned), zeros elsewhere. Zero c.
__global__ void init_kernel(const float* __restrict__ x) {
    int idx = blockIdx.x * blockDim.x + threadIdx.x;
    const int nA = BATCH * KP;
    const int total = nA + BATCH * PARTS * HID;
    for (; idx < total; idx += gridDim.x * blockDim.x) {
        if (idx < nA) {
            int b = idx / KP, k = idx % KP;
            float v = 0.0f;
            if (k < 160) {
                int p = k >> 5, d = k & 31;
                if (d < DP) v = x[((p * BATCH + b) * SEQ + 0) * DP + d];
            }
            write_A(b, k, v);
        } else {
            g_c[idx - nA] = 0.0f;
        }
    }
}

// ---------------------------------------------------------------------------
// Step GEMM: G[128,8192] = A[128,672] @ W[672,8192] + bias
// Gate n-blocks iterate 17 chunks (own x chunk + 16 h chunks); o_pre all 21.
// grid = (64 n-blocks, 2 m-blocks); 256 thr; 64x128 tile; warps 32x32;
// BK=32 (2 k16 slices); 3-stage cp.async pipeline; combo-major mma order.
// ---------------------------------------------------------------------------
__device__ __forceinline__ void mma16(float* d, const uint4& a, const uint2& b) {
    asm volatile(
        "mma.sync.aligned.m16n8k16.row.col.f32.bf16.bf16.f32 "
        "{%0,%1,%2,%3}, {%4,%5,%6,%7}, {%8,%9}, {%0,%1,%2,%3};"
        : "+f"(d[0]), "+f"(d[1]), "+f"(d[2]), "+f"(d[3])
        : "r"(a.x), "r"(a.y), "r"(a.z), "r"(a.w), "r"(b.x), "r"(b.y));
}
__device__ __forceinline__ void cp16(uint32_t* smem_dst, const void* gsrc) {
    uint32_t d = smem_u32(smem_dst);
    unsigned long long g = (unsigned long long)__cvta_generic_to_global(gsrc);
    asm volatile("cp.async.cg.shared.global [%0], [%1], 16;" :: "r"(d), "l"(g));
}

// stage layout (u32): Ah[0..1024) Al[1024..2048) Bh[2048..4096) Bl[4096..6144)
#define STAGE_U 6144          // 24 KB
#define NSTAGE  3

__device__ __forceinline__ void fill_stage(uint32_t* st, int j, int mb, int nblk,
                                           int tid) {
    const uint32_t* gAh = (const uint32_t*)g_Abf_hi;
    const uint32_t* gAl = (const uint32_t*)g_Abf_lo;
    const uint32_t* gBh = (const uint32_t*)g_Wb_hi;
    const uint32_t* gBl = (const uint32_t*)g_Wb_lo;
    {
        int i = tid;
        int slice = i >> 7, rem = i & 127;
        int mi_l = rem >> 5, lane = rem & 31;
        int gidx = (((j * 2 + slice) * 8 + mb * 4 + mi_l) * 32 + lane) * 4;
        int soff = slice * 512 + mi_l * 128 + lane * 4;
        cp16(st + soff,        gAh + gidx);
        cp16(st + 1024 + soff, gAl + gidx);
    }
#pragma unroll
    for (int i = tid; i < 512; i += 256) {
        int slice = i >> 8, rem = i & 255;
        size_t gidx = ((size_t)(nblk * NK16 + j * 2 + slice)) * 1024 + rem * 4;
        int soff = slice * 1024 + rem * 4;
        cp16(st + 2048 + soff, gBh + gidx);
        cp16(st + 4096 + soff, gBl + gidx);
    }
    asm volatile("cp.async.commit_group;");
}

__global__ void __launch_bounds__(256) gemm_kernel() {
    extern __shared__ uint32_t sm[];
    const int tid  = threadIdx.x;
    const int wid  = tid >> 5;
    const int lane = tid & 31;
    const int wm   = wid & 1;
    const int wn   = wid >> 1;
    const int nblk = blockIdx.x;
    const int mb   = blockIdx.y;

    // chunk schedule: gate blocks (nblk<60) -> {part x chunk, 5..20}; o_pre -> 0..20
    const bool opre = (nblk >= 60);
    const int  xchunk = nblk / 12;        // valid for gate blocks
    const int  nch = opre ? NCHUNK : NCH_GATE;
#define CHK(i) (opre ? (i) : ((i) == 0 ? xchunk : (i) + 4))

    float acc[2][4][4];
#pragma unroll
    for (int ms = 0; ms < 2; ms++)
#pragma unroll
        for (int ns = 0; ns < 4; ns++)
#pragma unroll
            for (int q = 0; q < 4; q++) acc[ms][ns][q] = 0.0f;

    fill_stage(sm, CHK(0), mb, nblk, tid);
    fill_stage(sm + STAGE_U, CHK(1), mb, nblk, tid);

    for (int j = 0; j < nch; j++) {
        if (j < nch - 1) asm volatile("cp.async.wait_group 1;");
        else             asm volatile("cp.async.wait_group 0;");
        __syncthreads();

        if (j + 2 < nch)
            fill_stage(sm + ((j + 2) % NSTAGE) * STAGE_U, CHK(j + 2), mb, nblk, tid);

        const uint32_t* st = sm + (j % NSTAGE) * STAGE_U;
#pragma unroll
        for (int slice = 0; slice < 2; slice++) {
            uint4 ah[2], al[2];
#pragma unroll
            for (int ms = 0; ms < 2; ms++) {
                int fi = slice * 512 + (wm * 2 + ms) * 128 + lane * 4;
                ah[ms] = *(const uint4*)(st + fi);
                al[ms] = *(const uint4*)(st + 1024 + fi);
            }
            uint2 bh[4], bl[4];
#pragma unroll
            for (int ns = 0; ns < 4; ns++) {
                int gi = slice * 1024 + (wn * 4 + ns) * 64 + lane * 2;
                bh[ns] = *(const uint2*)(st + 2048 + gi);
                bl[ns] = *(const uint2*)(st + 4096 + gi);
            }
            // combo-major: consecutive mma hit different accumulators
#pragma unroll
            for (int ms = 0; ms < 2; ms++)
#pragma unroll
                for (int ns = 0; ns < 4; ns++) mma16(acc[ms][ns], ah[ms], bh[ns]);
#pragma unroll
            for (int ms = 0; ms < 2; ms++)
#pragma unroll
                for (int ns = 0; ns < 4; ns++) mma16(acc[ms][ns], ah[ms], bl[ns]);
#pragma unroll
            for (int ms = 0; ms < 2; ms++)
#pragma unroll
                for (int ns = 0; ns < 4; ns++) mma16(acc[ms][ns], al[ms], bh[ns]);
        }
    }
#undef CHK

    // epilogue: D map c0:(g,2t) c1:(g,2t+1) c2:(g+8,2t) c3:(g+8,2t+1)
    const int g = lane >> 2, t = lane & 3;
#pragma unroll
    for (int ms = 0; ms < 2; ms++) {
        int m0 = mb * 64 + wm * 32 + ms * 16;
#pragma unroll
        for (int ns = 0; ns < 4; ns++) {
            int col = nblk * 128 + wn * 32 + ns * 8 + 2 * t;
            float2 bv = *(const float2*)&g_bias[col];
            float2 v0 = { acc[ms][ns][0] + bv.x, acc[ms][ns][1] + bv.y };
            float2 v1 = { acc[ms][ns][2] + bv.x, acc[ms][ns][3] + bv.y };
            *(float2*)&g_G[(size_t)(m0 + g)     * NB + col] = v0;
            *(float2*)&g_G[(size_t)(m0 + g + 8) * NB + col] = v1;
        }
    }
}

// ---------------------------------------------------------------------------
// Cell update. grid=(BATCH), block=(HID). h at k=160+hh; x at k=32p+d.
// ---------------------------------------------------------------------------
__global__ void cell_kernel(const float* __restrict__ x, int t) {
    const int b  = blockIdx.x;
    const int hh = threadIdx.x;
    const float* Gr = g_G + (size_t)b * NB;

    float csum = 0.0f;
#pragma unroll
    for (int p = 0; p < PARTS; p++) {
        float iv = Gr[p * GATES3 + hh];
        float fv = Gr[p * GATES3 + HID + hh];
        float gv = Gr[p * GATES3 + 2 * HID + hh];
        float co = g_c[(b * PARTS + p) * HID + hh];
        float cn = sigf(fv) * co + sigf(iv) * tanhf(gv);
        g_c[(b * PARTS + p) * HID + hh] = cn;
        csum += cn;
    }
    float o  = sigf(Gr[PARTS * GATES3 + hh]);
    float hv = o * tanhf(csum);
    g_h[b * HID + hh] = hv;
    write_A(b, 160 + hh, hv);

    if (hh < IN_DIM && t + 1 < SEQ) {
        int p = hh / DP, d = hh % DP;
        write_A(b, 32 * p + d, x[((p * BATCH + b) * SEQ + (t + 1)) * DP + d]);
    }
}

// ---------------------------------------------------------------------------
// Classifier + log_softmax. grid=(BATCH), block=(64).
// ---------------------------------------------------------------------------
__global__ void head_kernel(const float* __restrict__ fc_w, const float* __restrict__ fc_b,
                            float* __restrict__ out) {
    __shared__ float logits[CLASSES];
    const int b = blockIdx.x;
    const int c = threadIdx.x;
    if (c < CLASSES) {
        float acc = fc_b[c];
        const float* h = g_h + b * HID;
        for (int k = 0; k < HID; k++) acc += h[k] * fc_w[k * CLASSES + c];
        logits[c] = acc;
    }
    __syncthreads();
    if (c < CLASSES) {
        float m = -1e30f;
        for (int j = 0; j < CLASSES; j++) m = fmaxf(m, logits[j]);
        float s = 0.0f;
        for (int j = 0; j < CLASSES; j++) s += expf(logits[j] - m);
        out[b * CLASSES + c] = logits[c] - m - logf(s);
    }
}

extern "C" void kernel_launch(void* const* d_in, const int* in_sizes, int n_in,
                              void* d_out, int out_size) {
    const float* inputs = (const float*)d_in[0];
    const float* Wx     = (const float*)d_in[1];
    const float* Wh     = (const float*)d_in[2];
    const float* bvec   = (const float*)d_in[3];
    const float* Wxo    = (const float*)d_in[4];
    const float* Who    = (const float*)d_in[5];
    const float* bo     = (const float*)d_in[6];
    const float* fc_w   = (const float*)d_in[7];
    const float* fc_b   = (const float*)d_in[8];
    float* out = (float*)d_out;

    static int smem_set = 0;
    if (!smem_set) {
        cudaFuncSetAttribute(gemm_kernel, cudaFuncAttributeMaxDynamicSharedMemorySize,
                             NSTAGE * STAGE_U * sizeof(uint32_t));
        smem_set = 1;
    }

    pack_kernel<<<2048, 256>>>(Wx, Wh, Wxo, Who);
    bias_kernel<<<(NB + 255) / 256, 256>>>(bvec, bo);
    init_kernel<<<512, 256>>>(inputs);

    dim3 ggrid(64, 2);
    for (int t = 0; t < SEQ; t++) {
        gemm_kernel<<<ggrid, 256, NSTAGE * STAGE_U * sizeof(uint32_t)>>>();
        cell_kernel<<<BATCH, HID>>>(inputs, t);
    }

    head_kernel<<<BATCH, 64>>>(fc_w, fc_b, out);
}

// round 12
// speedup vs baseline: 3.0809x; 1.0844x over previous
#include <cuda_runtime.h>
#include <cuda_bf16.h>
#include <math.h>
#include <stdint.h>

// Problem constants
#define PARTS   5
#define BATCH   128
#define SEQ     300
#define DP      30
#define HID     512
#define CLASSES 60
#define IN_DIM  150
#define GATES3  1536
#define NB      8192          // 5*1536 gate cols + 512 o_pre cols
// K layout: part p x-inputs at k in [32p, 32p+30), pad to 32; h at [160, 672).
#define KP      672
#define NK16    42
#define NCHUNK  21
#define NCH_GATE 17           // gate n-blocks: 1 x chunk + 16 h chunks

// ---- device globals (no allocation allowed) --------------------------------
// A operand fragment-major (bf16): [k16 0..41][mi 0..7][lane 0..31][4 regs x 2]
__device__ __nv_bfloat16 g_Abf_hi[KP * BATCH];
__device__ __nv_bfloat16 g_Abf_lo[KP * BATCH];
// B operand fragment-major (bf16): [nblk64 0..127][k16][ni 0..7][lane][2 regs x 2]
__device__ __nv_bfloat16 g_Wb_hi[(size_t)KP * NB];   // 11 MB
__device__ __nv_bfloat16 g_Wb_lo[(size_t)KP * NB];   // 11 MB
__device__ float g_bias[NB];
__device__ float g_h[BATCH * HID];
__device__ float g_G[BATCH * NB];
__device__ float g_c[BATCH * PARTS * HID];

__device__ __forceinline__ float sigf(float x) { return 1.0f / (1.0f + expf(-x)); }
__device__ __forceinline__ uint32_t smem_u32(const void* p) {
    uint32_t a;
    asm("{ .reg .u64 t; cvta.to.shared.u64 t, %1; cvt.u32.u64 %0, t; }" : "=r"(a) : "l"(p));
    return a;
}

// Write fp32 v (split hi/lo bf16) at logical A position (batch b, k).
__device__ __forceinline__ void write_A(int b, int k, float v) {
    int k16 = k >> 4, c = k & 15;
    int mi = b >> 4, r = b & 15;
    int g = r & 7, t = (c & 7) >> 1;
    int lane = g * 4 + t;
    int reg = (r >> 3) + 2 * (c >> 3);
    int half = c & 1;
    int idx = (((k16 * 8 + mi) * 32 + lane) * 4 + reg) * 2 + half;
    __nv_bfloat16 hi = __float2bfloat16_rn(v);
    g_Abf_hi[idx] = hi;
    g_Abf_lo[idx] = __float2bfloat16_rn(v - __bfloat162float(hi));
}

// ---------------------------------------------------------------------------
// Pack weights into B-fragment-major split layout (64-col n-blocks).
//   K map: k<160: p=k>>5,d=k&31 (x of part p; d>=30 -> 0); k>=160: h input.
// ---------------------------------------------------------------------------
__global__ void pack_kernel(const float* __restrict__ Wx, const float* __restrict__ Wh,
                            const float* __restrict__ Wxo, const float* __restrict__ Who) {
    size_t idx = blockIdx.x * (size_t)blockDim.x + threadIdx.x;
    const size_t total = (size_t)KP * NB;
    for (; idx < total; idx += gridDim.x * (size_t)blockDim.x) {
        int k = (int)(idx / NB), n = (int)(idx % NB);
        float v = 0.0f;
        if (n < PARTS * GATES3) {
            int pc = n / GATES3, gi = n % GATES3;
            if (k < 160) {
                int p = k >> 5, d = k & 31;
                if (p == pc && d < DP) v = Wx[(pc * DP + d) * GATES3 + gi];
            } else {
                v = Wh[(pc * HID + (k - 160)) * GATES3 + gi];
            }
        } else {
            int j = n - PARTS * GATES3;
            if (k < 160) {
                int p = k >> 5, d = k & 31;
                if (d < DP) v = Wxo[(p * DP + d) * HID + j];
            } else {
                v = Who[(k - 160) * HID + j];
            }
        }
        int nblk = n >> 6, nn = n & 63;
        int ni = nn >> 3, g = nn & 7;
        int k16 = k >> 4, c = k & 15;
        int t = (c & 7) >> 1, half = c & 1, reg = c >> 3;
        int lane = g * 4 + t;
        size_t off = (((size_t)(nblk * NK16 + k16) * 8 + ni) * 32 + lane) * 4
                   + reg * 2 + half;
        __nv_bfloat16 hi = __float2bfloat16_rn(v);
        g_Wb_hi[off] = hi;
        g_Wb_lo[off] = __float2bfloat16_rn(v - __bfloat162float(hi));
    }
}

__global__ void bias_kernel(const float* __restrict__ bvec, const float* __restrict__ bo) {
    int n = blockIdx.x * blockDim.x + threadIdx.x;
    if (n >= NB) return;
    if (n < PARTS * GATES3) g_bias[n] = bvec[(n / GATES3) * GATES3 + (n % GATES3)];
    else                    g_bias[n] = bo[n - PARTS * GATES3];
}

// A(t=0): x_0 at k<160 (per-part 32-aligned), zeros elsewhere. Zero c.
__global__ void init_kernel(const float* __restrict__ x) {
    int idx = blockIdx.x * blockDim.x + threadIdx.x;
    const int nA = BATCH * KP;
    const int total = nA + BATCH * PARTS * HID;
    for (; idx < total; idx += gridDim.x * blockDim.x) {
        if (idx < nA) {
            int b = idx / KP, k = idx % KP;
            float v = 0.0f;
            if (k < 160) {
                int p = k >> 5, d = k & 31;
                if (d < DP) v = x[((p * BATCH + b) * SEQ + 0) * DP + d];
            }
            write_A(b, k, v);
        } else {
            g_c[idx - nA] = 0.0f;
        }
    }
}

// ---------------------------------------------------------------------------
// Step GEMM: G[128,8192] = A[128,672] @ W[672,8192] + bias
// grid = (128 n-blocks of 64, 2 m-blocks of 64); 128 thr (4 warps, 2m x 2n,
// warp tile 32x32); BK=32; 4-stage cp.async pipeline; 2 CTAs co-resident/SM.
// ---------------------------------------------------------------------------
__device__ __forceinline__ void mma16(float* d, const uint4& a, const uint2& b) {
    asm volatile(
        "mma.sync.aligned.m16n8k16.row.col.f32.bf16.bf16.f32 "
        "{%0,%1,%2,%3}, {%4,%5,%6,%7}, {%8,%9}, {%0,%1,%2,%3};"
        : "+f"(d[0]), "+f"(d[1]), "+f"(d[2]), "+f"(d[3])
        : "r"(a.x), "r"(a.y), "r"(a.z), "r"(a.w), "r"(b.x), "r"(b.y));
}
__device__ __forceinline__ void cp16(uint32_t* smem_dst, const void* gsrc) {
    uint32_t d = smem_u32(smem_dst);
    unsigned long long g = (unsigned long long)__cvta_generic_to_global(gsrc);
    asm volatile("cp.async.cg.shared.global [%0], [%1], 16;" :: "r"(d), "l"(g));
}

// stage (u32): Ah[0,1024) Al[1024,2048) Bh[2048,3072) Bl[3072,4096) = 16 KB
#define STAGE_U 4096
#define NSTAGE  4

__device__ __forceinline__ void fill_stage(uint32_t* st, int j, int mb, int nblk,
                                           int tid) {
    const uint32_t* gAh = (const uint32_t*)g_Abf_hi;
    const uint32_t* gAl = (const uint32_t*)g_Abf_lo;
    const uint32_t* gBh = (const uint32_t*)g_Wb_hi;
    const uint32_t* gBl = (const uint32_t*)g_Wb_lo;
    // A: 2 slices x 4 mi x 32 lanes x 16B per split
#pragma unroll
    for (int i = tid; i < 256; i += 128) {
        int slice = i >> 7, rem = i & 127;
        int mi_l = rem >> 5, lane = rem & 31;
        int gidx = (((j * 2 + slice) * 8 + mb * 4 + mi_l) * 32 + lane) * 4;
        int soff = slice * 512 + mi_l * 128 + lane * 4;
        cp16(st + soff,        gAh + gidx);
        cp16(st + 1024 + soff, gAl + gidx);
    }
    // B: 2 slices x 512 u32 contiguous per split
#pragma unroll
    for (int i = tid; i < 256; i += 128) {
        int slice = i >> 7, rem = i & 127;
        size_t gidx = ((size_t)(nblk * NK16 + j * 2 + slice)) * 512 + rem * 4;
        int soff = slice * 512 + rem * 4;
        cp16(st + 2048 + soff, gBh + gidx);
        cp16(st + 3072 + soff, gBl + gidx);
    }
    asm volatile("cp.async.commit_group;");
}

__global__ void __launch_bounds__(128) gemm_kernel() {
    extern __shared__ uint32_t sm[];
    const int tid  = threadIdx.x;
    const int wid  = tid >> 5;
    const int lane = tid & 31;
    const int wm   = wid & 1;      // 2 m-warps
    const int wn   = wid >> 1;     // 2 n-warps
    const int nblk = blockIdx.x;   // 0..127 (64-col stripes)
    const int mb   = blockIdx.y;   // 0..1

    // chunk schedule: gate blocks (nblk<120): {part x chunk, 5..20}; o_pre: 0..20
    const bool opre = (nblk >= 120);
    const int  xchunk = nblk / 24;
    const int  nch = opre ? NCHUNK : NCH_GATE;
#define CHK(i) (opre ? (i) : ((i) == 0 ? xchunk : (i) + 4))

    float acc[2][4][4];
#pragma unroll
    for (int ms = 0; ms < 2; ms++)
#pragma unroll
        for (int ns = 0; ns < 4; ns++)
#pragma unroll
            for (int q = 0; q < 4; q++) acc[ms][ns][q] = 0.0f;

    fill_stage(sm,               CHK(0), mb, nblk, tid);
    fill_stage(sm + STAGE_U,     CHK(1), mb, nblk, tid);
    fill_stage(sm + 2 * STAGE_U, CHK(2), mb, nblk, tid);

    for (int j = 0; j < nch; j++) {
        int remaining = nch - j;
        if (remaining >= 3)      asm volatile("cp.async.wait_group 2;");
        else if (remaining == 2) asm volatile("cp.async.wait_group 1;");
        else                     asm volatile("cp.async.wait_group 0;");
        __syncthreads();

        if (j + 3 < nch)
            fill_stage(sm + ((j + 3) & 3) * STAGE_U, CHK(j + 3), mb, nblk, tid);

        const uint32_t* st = sm + (j & 3) * STAGE_U;
#pragma unroll
        for (int slice = 0; slice < 2; slice++) {
            uint4 ah[2], al[2];
#pragma unroll
            for (int ms = 0; ms < 2; ms++) {
                int fi = slice * 512 + (wm * 2 + ms) * 128 + lane * 4;
                ah[ms] = *(const uint4*)(st + fi);
                al[ms] = *(const uint4*)(st + 1024 + fi);
            }
            uint2 bh[4], bl[4];
#pragma unroll
            for (int ns = 0; ns < 4; ns++) {
                int gi = slice * 512 + (wn * 4 + ns) * 64 + lane * 2;
                bh[ns] = *(const uint2*)(st + 2048 + gi);
                bl[ns] = *(const uint2*)(st + 3072 + gi);
            }
            // combo-major: consecutive mma hit different accumulators
#pragma unroll
            for (int ms = 0; ms < 2; ms++)
#pragma unroll
                for (int ns = 0; ns < 4; ns++) mma16(acc[ms][ns], ah[ms], bh[ns]);
#pragma unroll
            for (int ms = 0; ms < 2; ms++)
#pragma unroll
                for (int ns = 0; ns < 4; ns++) mma16(acc[ms][ns], ah[ms], bl[ns]);
#pragma unroll
            for (int ms = 0; ms < 2; ms++)
#pragma unroll
                for (int ns = 0; ns < 4; ns++) mma16(acc[ms][ns], al[ms], bh[ns]);
        }
    }
#undef CHK

    // epilogue: D map c0:(g,2t) c1:(g,2t+1) c2:(g+8,2t) c3:(g+8,2t+1)
    const int g = lane >> 2, t = lane & 3;
#pragma unroll
    for (int ms = 0; ms < 2; ms++) {
        int m0 = mb * 64 + wm * 32 + ms * 16;
#pragma unroll
        for (int ns = 0; ns < 4; ns++) {
            int col = nblk * 64 + wn * 32 + ns * 8 + 2 * t;
            float2 bv = *(const float2*)&g_bias[col];
            float2 v0 = { acc[ms][ns][0] + bv.x, acc[ms][ns][1] + bv.y };
            float2 v1 = { acc[ms][ns][2] + bv.x, acc[ms][ns][3] + bv.y };
            *(float2*)&g_G[(size_t)(m0 + g)     * NB + col] = v0;
            *(float2*)&g_G[(size_t)(m0 + g + 8) * NB + col] = v1;
        }
    }
}

// ---------------------------------------------------------------------------
// Cell update. grid=(BATCH), block=(HID). h at k=160+hh; x at k=32p+d.
// ---------------------------------------------------------------------------
__global__ void cell_kernel(const float* __restrict__ x, int t) {
    const int b  = blockIdx.x;
    const int hh = threadIdx.x;
    const float* Gr = g_G + (size_t)b * NB;

    float csum = 0.0f;
#pragma unroll
    for (int p = 0; p < PARTS; p++) {
        float iv = Gr[p * GATES3 + hh];
        float fv = Gr[p * GATES3 + HID + hh];
        float gv = Gr[p * GATES3 + 2 * HID + hh];
        float co = g_c[(b * PARTS + p) * HID + hh];
        float cn = sigf(fv) * co + sigf(iv) * tanhf(gv);
        g_c[(b * PARTS + p) * HID + hh] = cn;
        csum += cn;
    }
    float o  = sigf(Gr[PARTS * GATES3 + hh]);
    float hv = o * tanhf(csum);
    g_h[b * HID + hh] = hv;
    write_A(b, 160 + hh, hv);

    if (hh < IN_DIM && t + 1 < SEQ) {
        int p = hh / DP, d = hh % DP;
        write_A(b, 32 * p + d, x[((p * BATCH + b) * SEQ + (t + 1)) * DP + d]);
    }
}

// ---------------------------------------------------------------------------
// Classifier + log_softmax. grid=(BATCH), block=(64).
// ---------------------------------------------------------------------------
__global__ void head_kernel(const float* __restrict__ fc_w, const float* __restrict__ fc_b,
                            float* __restrict__ out) {
    __shared__ float logits[CLASSES];
    const int b = blockIdx.x;
    const int c = threadIdx.x;
    if (c < CLASSES) {
        float acc = fc_b[c];
        const float* h = g_h + b * HID;
        for (int k = 0; k < HID; k++) acc += h[k] * fc_w[k * CLASSES + c];
        logits[c] = acc;
    }
    __syncthreads();
    if (c < CLASSES) {
        float m = -1e30f;
        for (int j = 0; j < CLASSES; j++) m = fmaxf(m, logits[j]);
        float s = 0.0f;
        for (int j = 0; j < CLASSES; j++) s += expf(logits[j] - m);
        out[b * CLASSES + c] = logits[c] - m - logf(s);
    }
}

extern "C" void kernel_launch(void* const* d_in, const int* in_sizes, int n_in,
                              void* d_out, int out_size) {
    const float* inputs = (const float*)d_in[0];
    const float* Wx     = (const float*)d_in[1];
    const float* Wh     = (const float*)d_in[2];
    const float* bvec   = (const float*)d_in[3];
    const float* Wxo    = (const float*)d_in[4];
    const float* Who    = (const float*)d_in[5];
    const float* bo     = (const float*)d_in[6];
    const float* fc_w   = (const float*)d_in[7];
    const float* fc_b   = (const float*)d_in[8];
    float* out = (float*)d_out;

    static int smem_set = 0;
    if (!smem_set) {
        cudaFuncSetAttribute(gemm_kernel, cudaFuncAttributeMaxDynamicSharedMemorySize,
                             NSTAGE * STAGE_U * sizeof(uint32_t));
        smem_set = 1;
    }

    pack_kernel<<<2048, 256>>>(Wx, Wh, Wxo, Who);
    bias_kernel<<<(NB + 255) / 256, 256>>>(bvec, bo);
    init_kernel<<<512, 256>>>(inputs);

    dim3 ggrid(128, 2);
    for (int t = 0; t < SEQ; t++) {
        gemm_kernel<<<ggrid, 128, NSTAGE * STAGE_U * sizeof(uint32_t)>>>();
        cell_kernel<<<BATCH, HID>>>(inputs, t);
    }

    head_kernel<<<BATCH, 64>>>(fc_w, fc_b, out);
}